// round 6
// baseline (speedup 1.0000x reference)
#include <cuda_runtime.h>
#include <math.h>

// Problem shape (fixed for this dataset): B=32, A=3, S=80, NC=80
#define NCLS   80
#define CH     85          // 5 + NC
#define TCH    6
#define S2     6400        // S*S
#define NA     3
#define EPSF   1e-7f

#define K1_BLOCKS 1184     // 8 blocks/SM x 148
#define K1_TPB    256
#define K1_THREADS (K1_BLOCKS * K1_TPB)

#define K2_BLOCKS 592      // 4 blocks/SM x 148
#define K2_TPB    256
#define K2_WARPS  (K2_BLOCKS * (K2_TPB / 32))

#define NWORDS_MAX 19200   // 614400 / 32

__device__ unsigned g_mask[NWORDS_MAX];
__device__ double   g_part1[K1_BLOCKS * 2];  // [nool_sum, noobj_cnt]
__device__ double   g_part2[K2_BLOCKS * 4];  // [box, objl, cls, obj_cnt]
__device__ unsigned g_done = 0;

__device__ __forceinline__ float warp_sum(float v) {
    #pragma unroll
    for (int o = 16; o; o >>= 1) v += __shfl_xor_sync(0xffffffffu, v, o);
    return v;
}
__device__ __forceinline__ float warp_max(float v) {
    #pragma unroll
    for (int o = 16; o; o >>= 1) v = fmaxf(v, __shfl_xor_sync(0xffffffffu, v, o));
    return v;
}
__device__ __forceinline__ double warp_sum_d(double v) {
    #pragma unroll
    for (int o = 16; o; o >>= 1) v += __shfl_xor_sync(0xffffffffu, v, o);
    return v;
}

// ===================== Kernel 1: lean dense scan =====================
// No-obj BCE on channel 0 for every cell + ballot masks of obj cells.
// <=32 regs -> 2048 threads/SM residency; 4 loads front-batched per thread.
__global__ __launch_bounds__(K1_TPB, 8)
void k_scan(const float* __restrict__ pred,
            const float* __restrict__ tgt,
            int cells)
{
    const int gtid = blockIdx.x * blockDim.x + threadIdx.x;
    const int lane = threadIdx.x & 31;

    float nool = 0.f, ncnt = 0.f;

    // two chunk slots per iteration for MLP (each thread sees ~2 cells total)
    for (int c = gtid; c < cells; c += 2 * K1_THREADS) {
        const int  c2 = c + K1_THREADS;
        const bool h2 = (c2 < cells);

        const float t0a = __ldg(&tgt[c * TCH]);
        const float p0a = __ldg(&pred[c * CH]);
        float t0b = -1.f, p0b = 0.f;
        if (h2) {
            t0b = __ldg(&tgt[c2 * TCH]);
            p0b = __ldg(&pred[c2 * CH]);
        }

        if (t0a == 0.0f) {
            nool += fmaxf(p0a, 0.f) + log1pf(expf(-fabsf(p0a)));
            ncnt += 1.f;
        }
        unsigned bala = __ballot_sync(0xffffffffu, t0a == 1.0f);
        if (lane == 0) g_mask[c >> 5] = bala;

        if (h2) {
            if (t0b == 0.0f) {
                nool += fmaxf(p0b, 0.f) + log1pf(expf(-fabsf(p0b)));
                ncnt += 1.f;
            }
        }
        unsigned balb = __ballot_sync(0xffffffffu, h2 && (t0b == 1.0f));
        if (h2 && lane == 0) g_mask[c2 >> 5] = balb;
    }

    nool = warp_sum(nool);
    ncnt = warp_sum(ncnt);

    __shared__ float sh[8][2];
    const int wid = threadIdx.x >> 5;
    if (lane == 0) { sh[wid][0] = nool; sh[wid][1] = ncnt; }
    __syncthreads();
    if (threadIdx.x == 0) {
        double d0 = 0.0, d1 = 0.0;
        #pragma unroll
        for (int w = 0; w < 8; w++) { d0 += (double)sh[w][0]; d1 += (double)sh[w][1]; }
        g_part1[blockIdx.x * 2 + 0] = d0;
        g_part1[blockIdx.x * 2 + 1] = d1;
    }
}

// ===================== Kernel 2: obj cells + final combine =====================
__device__ __forceinline__ void obj_loads(
    const float* __restrict__ pred, const float* __restrict__ tgt,
    int cc, int lane,
    float& v0, float& v1, float& v2, float& p0,
    float& p1, float& p2, float& p3, float& p4,
    float& t1, float& t2, float& t3, float& t4, float& t5)
{
    const int pb = cc * CH;
    const int tb = cc * TCH;
    v0 = __ldg(&pred[pb + 5  + lane]);
    v1 = __ldg(&pred[pb + 37 + lane]);
    v2 = (lane < 16) ? __ldg(&pred[pb + 69 + lane]) : 0.0f;
    p0 = __ldg(&pred[pb + 0]);
    p1 = __ldg(&pred[pb + 1]);
    p2 = __ldg(&pred[pb + 2]);
    p3 = __ldg(&pred[pb + 3]);
    p4 = __ldg(&pred[pb + 4]);
    t1 = __ldg(&tgt[tb + 1]);
    t2 = __ldg(&tgt[tb + 2]);
    t3 = __ldg(&tgt[tb + 3]);
    t4 = __ldg(&tgt[tb + 4]);
    t5 = __ldg(&tgt[tb + 5]);
}

__global__ __launch_bounds__(K2_TPB, 4)
void k_obj(const float* __restrict__ pred,
           const float* __restrict__ tgt,
           const float* __restrict__ anc,
           float* __restrict__ out,
           int cells)
{
    const int lane = threadIdx.x & 31;
    const int wg   = (blockIdx.x * blockDim.x + threadIdx.x) >> 5;
    const int nwords = cells >> 5;

    const float a0w = __ldg(&anc[0]), a0h = __ldg(&anc[1]);
    const float a1w = __ldg(&anc[2]), a1h = __ldg(&anc[3]);
    const float a2w = __ldg(&anc[4]), a2h = __ldg(&anc[5]);

    float a_box = 0.f, a_objl = 0.f, a_cls = 0.f, a_ocnt = 0.f;

    for (int w = wg; w < nwords; w += K2_WARPS) {
        unsigned bal = g_mask[w];
        if (!bal) continue;
        const int c0 = w << 5;
        if (lane == 0) a_ocnt += (float)__popc(bal);

        int i = __ffs(bal) - 1;
        bal &= bal - 1;
        float v0, v1, v2, p0, p1, p2, p3, p4, t1, t2, t3, t4, t5;
        obj_loads(pred, tgt, c0 + i, lane,
                  v0, v1, v2, p0, p1, p2, p3, p4, t1, t2, t3, t4, t5);

        while (true) {
            const int cur = c0 + i;
            const float w0 = v0, w1 = v1, w2 = v2, r0 = p0;
            const float q1 = p1, q2 = p2, q3 = p3, q4 = p4;
            const float u1 = t1, u2 = t2, u3 = t3, u4 = t4, u5 = t5;
            const bool more = (bal != 0);
            if (more) {
                i = __ffs(bal) - 1;
                bal &= bal - 1;
                obj_loads(pred, tgt, c0 + i, lane,
                          v0, v1, v2, p0, p1, p2, p3, p4, t1, t2, t3, t4, t5);
            }

            const bool has2 = (lane < 16);
            // log-softmax over 80 class logits
            float mx = fmaxf(fmaxf(w0, w1), has2 ? w2 : -INFINITY);
            mx = warp_max(mx);
            float e  = expf(w0 - mx) + expf(w1 - mx) + (has2 ? expf(w2 - mx) : 0.f);
            float sx = w0 + w1 + (has2 ? w2 : 0.f);
            e  = warp_sum(e);
            sx = warp_sum(sx);
            const float lse = mx + logf(e);

            const int k = (int)u5;
            const float xk = __ldg(&pred[cur * CH + 5 + k]);  // L1/L2 hit
            const float logpy   = xk - lse;
            const float sumlogp = sx - (float)NCLS * lse;
            const float ce = -(0.9f * logpy + (0.1f / (float)NCLS) * sumlogp);

            // object loss: BCE-with-logits of sigmoid(p0), t=1 (reference quirk)
            const float sg = 1.f / (1.f + expf(-r0));
            const float ol = fmaxf(sg, 0.f) - sg + log1pf(expf(-fabsf(sg)));

            // decoded box + CIoU
            const int aidx = (cur / S2) % NA;
            const float aw = (aidx == 0) ? a0w : ((aidx == 1) ? a1w : a2w);
            const float ah = (aidx == 0) ? a0h : ((aidx == 1) ? a1h : a2h);
            const float bx = 1.f / (1.f + expf(-q1));
            const float by = 1.f / (1.f + expf(-q2));
            const float bw = expf(q3) * aw;
            const float bh = expf(q4) * ah;

            const float x1a = bx - bw * 0.5f, x1b = bx + bw * 0.5f;
            const float y1a = by - bh * 0.5f, y1b = by + bh * 0.5f;
            const float x2a = u1 - u3 * 0.5f, x2b = u1 + u3 * 0.5f;
            const float y2a = u2 - u4 * 0.5f, y2b = u2 + u4 * 0.5f;
            const float iw = fmaxf(fminf(x1b, x2b) - fmaxf(x1a, x2a), 0.f);
            const float ih = fmaxf(fminf(y1b, y2b) - fmaxf(y1a, y2a), 0.f);
            const float inter = iw * ih;
            const float uni = bw * bh + u3 * u4 - inter + EPSF;
            const float iou = inter / uni;
            const float cw  = fmaxf(x1b, x2b) - fminf(x1a, x2a);
            const float chh = fmaxf(y1b, y2b) - fminf(y1a, y2a);
            const float c2  = cw * cw + chh * chh + EPSF;
            const float rho2 = (u1 - bx) * (u1 - bx) + (u2 - by) * (u2 - by);
            const float fo = 4.0f / ((float)M_PI * (float)M_PI);
            const float dv = atanf(u3 / (u4 + EPSF)) - atanf(bw / (bh + EPSF));
            const float v  = fo * dv * dv;
            const float alpha = v / (1.f - iou + v + EPSF);
            const float ciou  = iou - rho2 / c2 - alpha * v;

            if (lane == 0) {
                a_box  += (1.f - ciou);
                a_objl += ol;
                a_cls  += ce;
            }
            if (!more) break;
        }
    }

    a_box  = warp_sum(a_box);
    a_objl = warp_sum(a_objl);
    a_cls  = warp_sum(a_cls);
    a_ocnt = warp_sum(a_ocnt);

    __shared__ float sh[8][4];
    const int wid = threadIdx.x >> 5;
    if (lane == 0) {
        sh[wid][0] = a_box; sh[wid][1] = a_objl;
        sh[wid][2] = a_cls; sh[wid][3] = a_ocnt;
    }
    __syncthreads();

    __shared__ bool amlast;
    if (threadIdx.x == 0) {
        #pragma unroll
        for (int q = 0; q < 4; q++) {
            double d = 0.0;
            #pragma unroll
            for (int wdx = 0; wdx < 8; wdx++) d += (double)sh[wdx][q];
            g_part2[blockIdx.x * 4 + q] = d;
        }
        __threadfence();
        const unsigned old = atomicAdd(&g_done, 1u);
        amlast = (old == (unsigned)(gridDim.x - 1));
    }
    __syncthreads();

    if (amlast) {
        __threadfence();
        // sum kernel-1 partials (nool, ncnt) and kernel-2 partials (box, objl, cls, ocnt)
        double acc[6] = {0, 0, 0, 0, 0, 0};
        volatile double* gp1 = g_part1;
        volatile double* gp2 = g_part2;
        for (int i = threadIdx.x; i < K1_BLOCKS; i += K2_TPB) {
            acc[0] += gp1[i * 2 + 0];
            acc[1] += gp1[i * 2 + 1];
        }
        for (int i = threadIdx.x; i < K2_BLOCKS; i += K2_TPB) {
            acc[2] += gp2[i * 4 + 0];
            acc[3] += gp2[i * 4 + 1];
            acc[4] += gp2[i * 4 + 2];
            acc[5] += gp2[i * 4 + 3];
        }
        #pragma unroll
        for (int q = 0; q < 6; q++) acc[q] = warp_sum_d(acc[q]);

        __shared__ double fsh[8][6];
        if (lane == 0) {
            #pragma unroll
            for (int q = 0; q < 6; q++) fsh[wid][q] = acc[q];
        }
        __syncthreads();
        if (threadIdx.x == 0) {
            double tot[6] = {0, 0, 0, 0, 0, 0};
            #pragma unroll
            for (int wdx = 0; wdx < 8; wdx++)
                #pragma unroll
                for (int q = 0; q < 6; q++) tot[q] += fsh[wdx][q];
            const double nool = tot[0] / fmax(tot[1], 1.0);
            const double od   = fmax(tot[5], 1.0);
            out[0] = (float)(2.0 * (tot[2] / od) + tot[3] / od + nool + tot[4] / od);
            __threadfence();
            g_done = 0;  // reset for next graph replay
        }
    }
}

extern "C" void kernel_launch(void* const* d_in, const int* in_sizes, int n_in,
                              void* d_out, int out_size)
{
    (void)n_in; (void)out_size;
    const float* pred = (const float*)d_in[0];
    const float* tgt  = (const float*)d_in[1];
    const float* anc  = (const float*)d_in[2];
    float* out = (float*)d_out;

    const int cells = in_sizes[0] / CH;   // 614400

    k_scan<<<K1_BLOCKS, K1_TPB>>>(pred, tgt, cells);
    k_obj<<<K2_BLOCKS, K2_TPB>>>(pred, tgt, anc, out, cells);
}